// round 6
// baseline (speedup 1.0000x reference)
#include <cuda_runtime.h>
#include <math.h>

#define TT      2048
#define H2      2048
#define G4      8192      // 4 * H2 gate rows
#define LAYERS  4

#define RBLOCKS  128      // persistent recurrence blocks (<= #SMs, co-resident)
#define RTHREADS 512      // 16 warps
#define JPB      16       // H2 / RBLOCKS hidden units per block (4 gate rows each)

// ---------------- device scratch (static: no allocation anywhere) ----------------
__device__ float g_xw[(size_t)TT * G4];     // 64 MB: input-to-hidden + bias, per layer
__device__ float g_hseq[(size_t)TT * H2];   // 16 MB: h sequence of current layer
__device__ float g_bias[LAYERS * G4];       // b_ih + b_hh
__device__ unsigned int g_bar_count = 0;
__device__ unsigned int g_bar_epoch = 0;

// ---------------- software grid barrier (replay-invariant: epoch is cumulative) ----
__device__ __forceinline__ void grid_barrier()
{
    __syncthreads();
    if (threadIdx.x == 0) {
        unsigned e = *((volatile unsigned int*)&g_bar_epoch);
        __threadfence();
        unsigned a = atomicAdd(&g_bar_count, 1u);
        if (a == RBLOCKS - 1) {
            atomicExch(&g_bar_count, 0u);
            __threadfence();
            atomicAdd(&g_bar_epoch, 1u);
        } else {
            while (*((volatile unsigned int*)&g_bar_epoch) == e) { __nanosleep(64); }
        }
        __threadfence();
    }
    __syncthreads();
}

__device__ __forceinline__ float sigf(float x) { return 1.0f / (1.0f + expf(-x)); }

// ---------------- bias precompute: g_bias = b_ih + b_hh ----------------
__global__ void bias_kernel(const float* __restrict__ b_ih, const float* __restrict__ b_hh)
{
    int i = blockIdx.x * blockDim.x + threadIdx.x;
    if (i < LAYERS * G4) g_bias[i] = b_ih[i] + b_hh[i];
}

// ---------------- layer-0 xw: xw[t][r] = event[t] * w_ih0[r] + bias0[r] ----------------
__global__ void xw0_kernel(const float* __restrict__ event, const float* __restrict__ w_ih0)
{
    int t = blockIdx.x;
    float e = event[t];
    float4* dst = (float4*)(g_xw + (size_t)t * G4);
    const float4* w4 = (const float4*)w_ih0;
    const float4* b4 = (const float4*)g_bias;
    for (int i = threadIdx.x; i < G4 / 4; i += blockDim.x) {
        float4 w = w4[i], b = b4[i];
        dst[i] = make_float4(fmaf(e, w.x, b.x), fmaf(e, w.y, b.y),
                             fmaf(e, w.z, b.z), fmaf(e, w.w, b.w));
    }
}

// ---------------- xw GEMM for layers 1..3: xw = hseq @ w_ih[l-1]^T + bias[l] ----------------
// C[M=2048(t)][N=8192(r)] = A[M][K=2048] * B[N][K]^T. 128x128x16 tile, 256 thr, 8x8 micro.
__global__ void __launch_bounds__(256)
xw_gemm_kernel(const float* __restrict__ B, int layer)
{
    __shared__ float As[16][128];
    __shared__ float Bs[16][128];
    const float* A = g_hseq;
    const float* bias = g_bias + (size_t)layer * G4;
    const int K = H2;
    int tid = threadIdx.x;
    int tx = tid & 15, ty = tid >> 4;
    int m0 = blockIdx.y * 128, n0 = blockIdx.x * 128;

    float acc[8][8];
#pragma unroll
    for (int i = 0; i < 8; i++)
#pragma unroll
        for (int j = 0; j < 8; j++) acc[i][j] = 0.f;

    for (int k0 = 0; k0 < K; k0 += 16) {
#pragma unroll
        for (int jj = 0; jj < 2; jj++) {
            int id = tid + jj * 256;           // 0..511
            int m  = id >> 2;                  // 0..127
            int kq = (id & 3) * 4;             // 0,4,8,12
            float4 a = *(const float4*)(A + (size_t)(m0 + m) * K + k0 + kq);
            As[kq + 0][m] = a.x; As[kq + 1][m] = a.y; As[kq + 2][m] = a.z; As[kq + 3][m] = a.w;
            float4 b = *(const float4*)(B + (size_t)(n0 + m) * K + k0 + kq);
            Bs[kq + 0][m] = b.x; Bs[kq + 1][m] = b.y; Bs[kq + 2][m] = b.z; Bs[kq + 3][m] = b.w;
        }
        __syncthreads();
#pragma unroll
        for (int kk = 0; kk < 16; kk++) {
            float af[8], bf[8];
            *(float4*)&af[0] = *(const float4*)&As[kk][ty * 8];
            *(float4*)&af[4] = *(const float4*)&As[kk][ty * 8 + 4];
            *(float4*)&bf[0] = *(const float4*)&Bs[kk][tx * 8];
            *(float4*)&bf[4] = *(const float4*)&Bs[kk][tx * 8 + 4];
#pragma unroll
            for (int i = 0; i < 8; i++)
#pragma unroll
                for (int j = 0; j < 8; j++) acc[i][j] = fmaf(af[i], bf[j], acc[i][j]);
        }
        __syncthreads();
    }

#pragma unroll
    for (int i = 0; i < 8; i++) {
        int m = m0 + ty * 8 + i;
#pragma unroll
        for (int j = 0; j < 8; j += 4) {
            int n = n0 + tx * 8 + j;
            float4 o;
            o.x = acc[i][j + 0] + bias[n + 0];
            o.y = acc[i][j + 1] + bias[n + 1];
            o.z = acc[i][j + 2] + bias[n + 2];
            o.w = acc[i][j + 3] + bias[n + 3];
            *(float4*)(g_xw + (size_t)m * G4 + n) = o;
        }
    }
}

// ---------------- persistent LSTM recurrence: one layer, all T steps ----------------
// Each block owns 16 hidden units (64 gate rows). Grid barrier each step.
__global__ void __launch_bounds__(RTHREADS, 1)
lstm_layer_kernel(const float* __restrict__ whh)
{
    __shared__ float hbuf[H2];
    __shared__ float gate_sm[64];
    __shared__ float c_sm[JPB];
    const int tid   = threadIdx.x;
    const int wid   = tid >> 5;
    const int lane  = tid & 31;
    const int jbase = blockIdx.x * JPB;

    if (tid < JPB) c_sm[tid] = 0.f;
    __syncthreads();

    for (int t = 0; t < TT; ++t) {
        if (t == 0) {
            // h = 0 -> gates = xw[0]
            if (tid < 64) {
                int gate = tid >> 4, jl = tid & 15;
                gate_sm[tid] = g_xw[(size_t)0 * G4 + gate * H2 + jbase + jl];
            }
            __syncthreads();
        } else {
            // stage h_{t-1} (written by all blocks last step) into SMEM
            const float4* hp = (const float4*)(g_hseq + (size_t)(t - 1) * H2);
            ((float4*)hbuf)[tid] = hp[tid];   // 512 threads x float4 = 2048 floats
            __syncthreads();
            const float4* hb = (const float4*)hbuf;
            // each warp: 4 gate rows, 2048-wide dot each
#pragma unroll
            for (int rr = 0; rr < 4; ++rr) {
                int lr   = wid * 4 + rr;          // 0..63
                int gate = lr >> 4, jl = lr & 15;
                int grow = gate * H2 + jbase + jl;
                const float4* w4 = (const float4*)(whh + (size_t)grow * H2);
                float s0 = 0.f, s1 = 0.f, s2 = 0.f, s3 = 0.f;
#pragma unroll
                for (int i = 0; i < 16; ++i) {
                    float4 w = w4[lane + 32 * i];
                    float4 h = hb[lane + 32 * i];
                    s0 = fmaf(w.x, h.x, s0);
                    s1 = fmaf(w.y, h.y, s1);
                    s2 = fmaf(w.z, h.z, s2);
                    s3 = fmaf(w.w, h.w, s3);
                }
                float v = (s0 + s1) + (s2 + s3);
#pragma unroll
                for (int o = 16; o > 0; o >>= 1) v += __shfl_down_sync(0xffffffffu, v, o);
                if (lane == 0) gate_sm[lr] = v + g_xw[(size_t)t * G4 + grow];
            }
            __syncthreads();
        }
        // cell/hidden update for this block's 16 units
        if (tid < JPB) {
            float xi = gate_sm[tid];
            float xf = gate_sm[16 + tid];
            float xg = gate_sm[32 + tid];
            float xo = gate_sm[48 + tid];
            float c  = sigf(xf) * c_sm[tid] + sigf(xi) * tanhf(xg);
            c_sm[tid] = c;
            float h = sigf(xo) * tanhf(c);
            g_hseq[(size_t)t * H2 + jbase + tid] = h;
            __threadfence();
        }
        grid_barrier();
    }
}

// ---------------- output: logits = h_last @ w_out^T + b_out; log_softmax ----------------
__global__ void out_kernel(const float* __restrict__ w_out, const float* __restrict__ b_out,
                           float* __restrict__ out)
{
    __shared__ float red[16];
    const float* h = g_hseq + (size_t)(TT - 1) * H2;
    int tid = threadIdx.x, wid = tid >> 5, lane = tid & 31;
    float s0 = 0.f, s1 = 0.f;
    for (int k = tid; k < H2; k += 256) {
        float hv = h[k];
        s0 = fmaf(hv, w_out[k], s0);
        s1 = fmaf(hv, w_out[H2 + k], s1);
    }
#pragma unroll
    for (int o = 16; o > 0; o >>= 1) {
        s0 += __shfl_down_sync(0xffffffffu, s0, o);
        s1 += __shfl_down_sync(0xffffffffu, s1, o);
    }
    if (lane == 0) { red[wid] = s0; red[8 + wid] = s1; }
    __syncthreads();
    if (tid == 0) {
        float l0 = b_out[0], l1 = b_out[1];
        for (int w = 0; w < 8; w++) { l0 += red[w]; l1 += red[8 + w]; }
        float m = fmaxf(l0, l1);
        float z = logf(expf(l0 - m) + expf(l1 - m));
        out[0] = (l0 - m) - z;
        out[1] = (l1 - m) - z;
    }
}

// ---------------- host ----------------
extern "C" void kernel_launch(void* const* d_in, const int* in_sizes, int n_in,
                              void* d_out, int out_size)
{
    const float *event = nullptr, *w_ih0 = nullptr, *w_ih = nullptr, *whh = nullptr;
    const float *b_ih = nullptr, *b_hh = nullptr, *w_out = nullptr, *b_out = nullptr;
    // map inputs by element count (robust to ordering; b_ih/b_hh are symmetric under +)
    for (int i = 0; i < n_in; i++) {
        long long s = in_sizes[i];
        const float* p = (const float*)d_in[i];
        if      (s == 2048)              event = p;
        else if (s == 8192)              w_ih0 = p;
        else if (s == 50331648LL)        w_ih  = p;   // 3*8192*2048
        else if (s == 67108864LL)        whh   = p;   // 4*8192*2048
        else if (s == 32768)             { if (!b_ih) b_ih = p; else b_hh = p; }
        else if (s == 4096)              w_out = p;
        else if (s == 2)                 b_out = p;
    }

    bias_kernel<<<(LAYERS * G4 + 255) / 256, 256>>>(b_ih, b_hh);
    xw0_kernel<<<TT, 256>>>(event, w_ih0);
    lstm_layer_kernel<<<RBLOCKS, RTHREADS>>>(whh);

    for (int l = 1; l < LAYERS; l++) {
        xw_gemm_kernel<<<dim3(G4 / 128, TT / 128), 256>>>(w_ih + (size_t)(l - 1) * G4 * H2, l);
        lstm_layer_kernel<<<RBLOCKS, RTHREADS>>>(whh + (size_t)l * G4 * H2);
    }

    out_kernel<<<1, 256>>>(w_out, b_out, (float*)d_out);
}

// round 8
// speedup vs baseline: 1.1475x; 1.1475x over previous
#include <cuda_runtime.h>
#include <cuda_fp16.h>
#include <math.h>

#define TT      2048
#define H2      2048
#define G4      8192      // 4 * H2 gate rows
#define LAYERS  4

// ---- persistent fp16-SMEM recurrence config ----
#define UB      14                      // hidden units per block
#define NB      ((H2 + UB - 1) / UB)    // 147 blocks (<= 152 SMs, co-resident at 1 blk/SM)
#define RROWS   (UB * 4)                // 56 gate rows per block
#define RTH     448                     // 14 warps: warp u owns unit u
#define SMEM_DYN (RROWS * H2 * 2 + 512 * 4)   // 229376 w + 2048 h-chunk = 231424 B

// ---------------- device scratch (static: no allocation anywhere) ----------------
__device__ float  g_xw[(size_t)TT * G4];     // 64 MB: input-to-hidden + bias, per layer
__device__ float  g_hseq[(size_t)TT * H2];   // 16 MB: h sequence of current layer
__device__ float  g_bias[LAYERS * G4];       // b_ih + b_hh
__device__ __half g_wh16[(size_t)LAYERS * G4 * H2];  // 128 MB: W_hh fp16, unit-major rows
__device__ unsigned int g_bar_count = 0;
__device__ unsigned int g_bar_epoch = 0;

// ---------------- software grid barrier (replay-invariant: epoch is cumulative) ----
__device__ __forceinline__ void grid_barrier()
{
    __syncthreads();
    if (threadIdx.x == 0) {
        unsigned e = *((volatile unsigned int*)&g_bar_epoch);
        __threadfence();
        unsigned a = atomicAdd(&g_bar_count, 1u);
        if (a == NB - 1) {
            atomicExch(&g_bar_count, 0u);
            __threadfence();
            atomicAdd(&g_bar_epoch, 1u);
        } else {
            while (*((volatile unsigned int*)&g_bar_epoch) == e) { __nanosleep(64); }
        }
        __threadfence();
    }
    __syncthreads();
}

__device__ __forceinline__ float sigf(float x) { return 1.0f / (1.0f + expf(-x)); }

// ---------------- bias precompute: g_bias = b_ih + b_hh ----------------
__global__ void bias_kernel(const float* __restrict__ b_ih, const float* __restrict__ b_hh)
{
    int i = blockIdx.x * blockDim.x + threadIdx.x;
    if (i < LAYERS * G4) g_bias[i] = b_ih[i] + b_hh[i];
}

// ---------------- convert W_hh fp32 -> fp16, reorder rows to unit-major (j*4+g) ----
__global__ void convert_whh_kernel(const float* __restrict__ whh)
{
    int row   = blockIdx.x;              // 0 .. LAYERS*G4-1 (destination row order)
    int layer = row >> 13;
    int r     = row & 8191;
    int j     = r >> 2, g = r & 3;
    const float* src = whh + ((size_t)layer * G4 + (size_t)g * H2 + j) * H2;
    __half2* dst = (__half2*)(g_wh16 + (size_t)row * H2);
    int i = threadIdx.x * 4;             // 512 threads x 4 elems = 2048
    float4 v = *(const float4*)(src + i);
    dst[threadIdx.x * 2 + 0] = __floats2half2_rn(v.x, v.y);
    dst[threadIdx.x * 2 + 1] = __floats2half2_rn(v.z, v.w);
}

// ---------------- layer-0 xw: xw[t][r] = event[t] * w_ih0[r] + bias0[r] ----------------
__global__ void xw0_kernel(const float* __restrict__ event, const float* __restrict__ w_ih0)
{
    int t = blockIdx.x;
    float e = event[t];
    float4* dst = (float4*)(g_xw + (size_t)t * G4);
    const float4* w4 = (const float4*)w_ih0;
    const float4* b4 = (const float4*)g_bias;
    for (int i = threadIdx.x; i < G4 / 4; i += blockDim.x) {
        float4 w = w4[i], b = b4[i];
        dst[i] = make_float4(fmaf(e, w.x, b.x), fmaf(e, w.y, b.y),
                             fmaf(e, w.z, b.z), fmaf(e, w.w, b.w));
    }
}

// ---------------- xw GEMM for layers 1..3: xw = hseq @ w_ih[l-1]^T + bias[l] ----------------
__global__ void __launch_bounds__(256)
xw_gemm_kernel(const float* __restrict__ B, int layer)
{
    __shared__ float As[16][128];
    __shared__ float Bs[16][128];
    const float* A = g_hseq;
    const float* bias = g_bias + (size_t)layer * G4;
    const int K = H2;
    int tid = threadIdx.x;
    int tx = tid & 15, ty = tid >> 4;
    int m0 = blockIdx.y * 128, n0 = blockIdx.x * 128;

    float acc[8][8];
#pragma unroll
    for (int i = 0; i < 8; i++)
#pragma unroll
        for (int j = 0; j < 8; j++) acc[i][j] = 0.f;

    for (int k0 = 0; k0 < K; k0 += 16) {
#pragma unroll
        for (int jj = 0; jj < 2; jj++) {
            int id = tid + jj * 256;
            int m  = id >> 2;
            int kq = (id & 3) * 4;
            float4 a = *(const float4*)(A + (size_t)(m0 + m) * K + k0 + kq);
            As[kq + 0][m] = a.x; As[kq + 1][m] = a.y; As[kq + 2][m] = a.z; As[kq + 3][m] = a.w;
            float4 b = *(const float4*)(B + (size_t)(n0 + m) * K + k0 + kq);
            Bs[kq + 0][m] = b.x; Bs[kq + 1][m] = b.y; Bs[kq + 2][m] = b.z; Bs[kq + 3][m] = b.w;
        }
        __syncthreads();
#pragma unroll
        for (int kk = 0; kk < 16; kk++) {
            float af[8], bf[8];
            *(float4*)&af[0] = *(const float4*)&As[kk][ty * 8];
            *(float4*)&af[4] = *(const float4*)&As[kk][ty * 8 + 4];
            *(float4*)&bf[0] = *(const float4*)&Bs[kk][tx * 8];
            *(float4*)&bf[4] = *(const float4*)&Bs[kk][tx * 8 + 4];
#pragma unroll
            for (int i = 0; i < 8; i++)
#pragma unroll
                for (int j = 0; j < 8; j++) acc[i][j] = fmaf(af[i], bf[j], acc[i][j]);
        }
        __syncthreads();
    }

#pragma unroll
    for (int i = 0; i < 8; i++) {
        int m = m0 + ty * 8 + i;
#pragma unroll
        for (int j = 0; j < 8; j += 4) {
            int n = n0 + tx * 8 + j;
            float4 o;
            o.x = acc[i][j + 0] + bias[n + 0];
            o.y = acc[i][j + 1] + bias[n + 1];
            o.z = acc[i][j + 2] + bias[n + 2];
            o.w = acc[i][j + 3] + bias[n + 3];
            *(float4*)(g_xw + (size_t)m * G4 + n) = o;
        }
    }
}

// ---------------- persistent LSTM recurrence: fp16 weights resident in SMEM ----------------
// 147 blocks, 14 warps each; warp u owns hidden unit j = blk*14+u (4 gate rows).
// Per step: stage h_{t-1} in 4 chunks of 512 (2 KB buffer), dot from SMEM, warp-reduce,
// lane 0 does the cell update (c lives in lane 0's register), grid barrier.
__global__ void __launch_bounds__(RTH, 1)
lstm_fp16_kernel(int layer)
{
    extern __shared__ unsigned char smem_raw[];
    __half* w_sm = (__half*)smem_raw;                            // RROWS*H2 halfs
    float*  hch  = (float*)(smem_raw + (size_t)RROWS * H2 * 2);  // 512 floats

    const int tid  = threadIdx.x;
    const int wu   = tid >> 5;      // warp = local unit index
    const int lane = tid & 31;
    const int j0   = blockIdx.x * UB;
    const int ub   = min(UB, H2 - j0);
    const int j    = j0 + wu;
    const bool active = (wu < ub);

    // Stage this block's weights into SMEM (coalesced uint4)
    {
        const uint4* src = (const uint4*)(g_wh16 + ((size_t)layer * G4 + (size_t)j0 * 4) * H2);
        int n = ub * 4 * H2 / 8;
        for (int i = tid; i < n; i += RTH) ((uint4*)w_sm)[i] = src[i];
    }
    __syncthreads();

    float creg = 0.f;
    float4 r4 = make_float4(0.f, 0.f, 0.f, 0.f);

    for (int t = 0; t < TT; ++t) {
        // prefetch xw for this unit's 4 gates (lanes 0..3)
        float xwv = 0.f;
        if (active && lane < 4)
            xwv = g_xw[(size_t)t * G4 + (size_t)lane * H2 + j];

        float a0 = 0.f, a1 = 0.f, a2 = 0.f, a3 = 0.f;
        if (t > 0) {
            const float4* hsrc = (const float4*)(g_hseq + (size_t)(t - 1) * H2);
            if (tid < 128) r4 = hsrc[tid];                 // chunk 0
#pragma unroll 1
            for (int c = 0; c < 4; ++c) {
                __syncthreads();                            // readers of hch done
                if (tid < 128) ((float4*)hch)[tid] = r4;
                __syncthreads();                            // hch visible
                if (c < 3 && tid < 128) r4 = hsrc[(c + 1) * 128 + tid];  // prefetch next
                if (active) {
                    const __half* wr = w_sm + (size_t)(wu * 4) * H2 + c * 512;
#pragma unroll
                    for (int p = 0; p < 4; ++p) {
                        float4 hv = ((const float4*)hch)[p * 32 + lane];
                        // gate 0 (i)
                        {
                            uint2 wq = *(const uint2*)(wr + 0 * H2 + p * 128 + lane * 4);
                            float2 fa = __half22float2(*(__half2*)&wq.x);
                            float2 fb = __half22float2(*(__half2*)&wq.y);
                            a0 = fmaf(fa.x, hv.x, a0); a0 = fmaf(fa.y, hv.y, a0);
                            a0 = fmaf(fb.x, hv.z, a0); a0 = fmaf(fb.y, hv.w, a0);
                        }
                        // gate 1 (f)
                        {
                            uint2 wq = *(const uint2*)(wr + 1 * H2 + p * 128 + lane * 4);
                            float2 fa = __half22float2(*(__half2*)&wq.x);
                            float2 fb = __half22float2(*(__half2*)&wq.y);
                            a1 = fmaf(fa.x, hv.x, a1); a1 = fmaf(fa.y, hv.y, a1);
                            a1 = fmaf(fb.x, hv.z, a1); a1 = fmaf(fb.y, hv.w, a1);
                        }
                        // gate 2 (g)
                        {
                            uint2 wq = *(const uint2*)(wr + 2 * H2 + p * 128 + lane * 4);
                            float2 fa = __half22float2(*(__half2*)&wq.x);
                            float2 fb = __half22float2(*(__half2*)&wq.y);
                            a2 = fmaf(fa.x, hv.x, a2); a2 = fmaf(fa.y, hv.y, a2);
                            a2 = fmaf(fb.x, hv.z, a2); a2 = fmaf(fb.y, hv.w, a2);
                        }
                        // gate 3 (o)
                        {
                            uint2 wq = *(const uint2*)(wr + 3 * H2 + p * 128 + lane * 4);
                            float2 fa = __half22float2(*(__half2*)&wq.x);
                            float2 fb = __half22float2(*(__half2*)&wq.y);
                            a3 = fmaf(fa.x, hv.x, a3); a3 = fmaf(fa.y, hv.y, a3);
                            a3 = fmaf(fb.x, hv.z, a3); a3 = fmaf(fb.y, hv.w, a3);
                        }
                    }
                }
            }
        }

        if (active) {
            // butterfly: every lane ends with the full sum of each gate
#pragma unroll
            for (int off = 16; off; off >>= 1) {
                a0 += __shfl_xor_sync(0xffffffffu, a0, off);
                a1 += __shfl_xor_sync(0xffffffffu, a1, off);
                a2 += __shfl_xor_sync(0xffffffffu, a2, off);
                a3 += __shfl_xor_sync(0xffffffffu, a3, off);
            }
            float pre = xwv;
            if      (lane == 0) pre += a0;
            else if (lane == 1) pre += a1;
            else if (lane == 2) pre += a2;
            else if (lane == 3) pre += a3;
            float pi_ = __shfl_sync(0xffffffffu, pre, 0);
            float pf_ = __shfl_sync(0xffffffffu, pre, 1);
            float pg_ = __shfl_sync(0xffffffffu, pre, 2);
            float po_ = __shfl_sync(0xffffffffu, pre, 3);
            if (lane == 0) {
                creg = sigf(pf_) * creg + sigf(pi_) * tanhf(pg_);
                float hval = sigf(po_) * tanhf(creg);
                g_hseq[(size_t)t * H2 + j] = hval;
                __threadfence();
            }
        }
        grid_barrier();
    }
}

// ---------------- output: logits = h_last @ w_out^T + b_out; log_softmax ----------------
__global__ void out_kernel(const float* __restrict__ w_out, const float* __restrict__ b_out,
                           float* __restrict__ out)
{
    __shared__ float red[16];
    const float* h = g_hseq + (size_t)(TT - 1) * H2;
    int tid = threadIdx.x, wid = tid >> 5, lane = tid & 31;
    float s0 = 0.f, s1 = 0.f;
    for (int k = tid; k < H2; k += 256) {
        float hv = h[k];
        s0 = fmaf(hv, w_out[k], s0);
        s1 = fmaf(hv, w_out[H2 + k], s1);
    }
#pragma unroll
    for (int o = 16; o > 0; o >>= 1) {
        s0 += __shfl_down_sync(0xffffffffu, s0, o);
        s1 += __shfl_down_sync(0xffffffffu, s1, o);
    }
    if (lane == 0) { red[wid] = s0; red[8 + wid] = s1; }
    __syncthreads();
    if (tid == 0) {
        float l0 = b_out[0], l1 = b_out[1];
        for (int w = 0; w < 8; w++) { l0 += red[w]; l1 += red[8 + w]; }
        float m = fmaxf(l0, l1);
        float z = logf(expf(l0 - m) + expf(l1 - m));
        out[0] = (l0 - m) - z;
        out[1] = (l1 - m) - z;
    }
}

// ---------------- host ----------------
extern "C" void kernel_launch(void* const* d_in, const int* in_sizes, int n_in,
                              void* d_out, int out_size)
{
    const float *event = nullptr, *w_ih0 = nullptr, *w_ih = nullptr, *whh = nullptr;
    const float *b_ih = nullptr, *b_hh = nullptr, *w_out = nullptr, *b_out = nullptr;
    for (int i = 0; i < n_in; i++) {
        long long s = in_sizes[i];
        const float* p = (const float*)d_in[i];
        if      (s == 2048)              event = p;
        else if (s == 8192)              w_ih0 = p;
        else if (s == 50331648LL)        w_ih  = p;   // 3*8192*2048
        else if (s == 67108864LL)        whh   = p;   // 4*8192*2048
        else if (s == 32768)             { if (!b_ih) b_ih = p; else b_hh = p; }
        else if (s == 4096)              w_out = p;
        else if (s == 2)                 b_out = p;
    }

    cudaFuncSetAttribute(lstm_fp16_kernel,
                         cudaFuncAttributeMaxDynamicSharedMemorySize, SMEM_DYN);

    bias_kernel<<<(LAYERS * G4 + 255) / 256, 256>>>(b_ih, b_hh);
    convert_whh_kernel<<<LAYERS * G4, 512>>>(whh);
    xw0_kernel<<<TT, 256>>>(event, w_ih0);
    lstm_fp16_kernel<<<NB, RTH, SMEM_DYN>>>(0);

    for (int l = 1; l < LAYERS; l++) {
        xw_gemm_kernel<<<dim3(G4 / 128, TT / 128), 256>>>(w_ih + (size_t)(l - 1) * G4 * H2, l);
        lstm_fp16_kernel<<<NB, RTH, SMEM_DYN>>>(l);
    }

    out_kernel<<<1, 256>>>(w_out, b_out, (float*)d_out);
}

// round 9
// speedup vs baseline: 1.4015x; 1.2214x over previous
#include <cuda_runtime.h>
#include <cuda_fp16.h>
#include <math.h>

#define TT      2048
#define H2      2048
#define G4      8192      // 4 * H2 gate rows
#define LAYERS  4

// ---- persistent fp16-SMEM recurrence config ----
#define UB      14                      // hidden units per block
#define NB      ((H2 + UB - 1) / UB)    // 147 blocks (<= 152 SMs, co-resident)
#define RROWS   (UB * 4)                // 56 gate rows per block
#define RTH     448                     // 14 warps: warp u owns unit u
#define SMEM_DYN (RROWS * H2 * 2)       // 229376 B of fp16 weights

// ---------------- device scratch (static: no allocation anywhere) ----------------
__device__ float  g_xw[(size_t)TT * G4];     // 64 MB: input-to-hidden + bias, per layer
__device__ float  g_hseq[(size_t)TT * H2];   // 16 MB: h sequence of current layer
__device__ float  g_bias[LAYERS * G4];       // b_ih + b_hh
__device__ __half g_wh16[(size_t)LAYERS * G4 * H2];  // 128 MB: W_hh fp16, unit-major rows
__device__ unsigned int g_bar_count = 0;
__device__ unsigned int g_bar_epoch = 0;

// ---------------- grid barrier: acq_rel arrive + release epoch + acquire poll ------
// No MEMBAR.GPU / CCTL.IVALL in the steady path. Happens-before chain:
// writers' stores -> __syncthreads -> atom.acq_rel(count) -> red.release(epoch)
// -> ld.acquire(epoch) on pollers -> __syncthreads. Epoch is cumulative, so the
// kernel is replay-invariant under graph capture.
__device__ __forceinline__ void grid_barrier()
{
    __syncthreads();
    if (threadIdx.x == 0) {
        unsigned e;
        asm volatile("ld.relaxed.gpu.u32 %0, [%1];" : "=r"(e) : "l"(&g_bar_epoch));
        unsigned a;
        asm volatile("atom.acq_rel.gpu.add.u32 %0, [%1], %2;"
                     : "=r"(a) : "l"(&g_bar_count), "r"(1u) : "memory");
        if (a == NB - 1) {
            asm volatile("st.relaxed.gpu.u32 [%0], %1;" :: "l"(&g_bar_count), "r"(0u) : "memory");
            asm volatile("red.release.gpu.add.u32 [%0], %1;" :: "l"(&g_bar_epoch), "r"(1u) : "memory");
        } else {
            unsigned cur;
            do {
                asm volatile("ld.acquire.gpu.u32 %0, [%1];" : "=r"(cur) : "l"(&g_bar_epoch) : "memory");
            } while (cur == e);
        }
    }
    __syncthreads();
}

__device__ __forceinline__ float sigf(float x) { return 1.0f / (1.0f + expf(-x)); }

// ---------------- bias precompute: g_bias = b_ih + b_hh ----------------
__global__ void bias_kernel(const float* __restrict__ b_ih, const float* __restrict__ b_hh)
{
    int i = blockIdx.x * blockDim.x + threadIdx.x;
    if (i < LAYERS * G4) g_bias[i] = b_ih[i] + b_hh[i];
}

// ---------------- convert W_hh fp32 -> fp16, reorder rows to unit-major (j*4+g) ----
__global__ void convert_whh_kernel(const float* __restrict__ whh)
{
    int row   = blockIdx.x;              // destination row order
    int layer = row >> 13;
    int r     = row & 8191;
    int j     = r >> 2, g = r & 3;
    const float* src = whh + ((size_t)layer * G4 + (size_t)g * H2 + j) * H2;
    __half2* dst = (__half2*)(g_wh16 + (size_t)row * H2);
    int i = threadIdx.x * 4;
    float4 v = *(const float4*)(src + i);
    dst[threadIdx.x * 2 + 0] = __floats2half2_rn(v.x, v.y);
    dst[threadIdx.x * 2 + 1] = __floats2half2_rn(v.z, v.w);
}

// ---------------- layer-0 xw: xw[t][r] = event[t] * w_ih0[r] + bias0[r] ----------------
__global__ void xw0_kernel(const float* __restrict__ event, const float* __restrict__ w_ih0)
{
    int t = blockIdx.x;
    float e = event[t];
    float4* dst = (float4*)(g_xw + (size_t)t * G4);
    const float4* w4 = (const float4*)w_ih0;
    const float4* b4 = (const float4*)g_bias;
    for (int i = threadIdx.x; i < G4 / 4; i += blockDim.x) {
        float4 w = w4[i], b = b4[i];
        dst[i] = make_float4(fmaf(e, w.x, b.x), fmaf(e, w.y, b.y),
                             fmaf(e, w.z, b.z), fmaf(e, w.w, b.w));
    }
}

// ---------------- xw GEMM for layers 1..3: xw = hseq @ w_ih[l-1]^T + bias[l] ----------------
__global__ void __launch_bounds__(256)
xw_gemm_kernel(const float* __restrict__ B, int layer)
{
    __shared__ float As[16][128];
    __shared__ float Bs[16][128];
    const float* A = g_hseq;
    const float* bias = g_bias + (size_t)layer * G4;
    const int K = H2;
    int tid = threadIdx.x;
    int tx = tid & 15, ty = tid >> 4;
    int m0 = blockIdx.y * 128, n0 = blockIdx.x * 128;

    float acc[8][8];
#pragma unroll
    for (int i = 0; i < 8; i++)
#pragma unroll
        for (int j = 0; j < 8; j++) acc[i][j] = 0.f;

    for (int k0 = 0; k0 < K; k0 += 16) {
#pragma unroll
        for (int jj = 0; jj < 2; jj++) {
            int id = tid + jj * 256;
            int m  = id >> 2;
            int kq = (id & 3) * 4;
            float4 a = *(const float4*)(A + (size_t)(m0 + m) * K + k0 + kq);
            As[kq + 0][m] = a.x; As[kq + 1][m] = a.y; As[kq + 2][m] = a.z; As[kq + 3][m] = a.w;
            float4 b = *(const float4*)(B + (size_t)(n0 + m) * K + k0 + kq);
            Bs[kq + 0][m] = b.x; Bs[kq + 1][m] = b.y; Bs[kq + 2][m] = b.z; Bs[kq + 3][m] = b.w;
        }
        __syncthreads();
#pragma unroll
        for (int kk = 0; kk < 16; kk++) {
            float af[8], bf[8];
            *(float4*)&af[0] = *(const float4*)&As[kk][ty * 8];
            *(float4*)&af[4] = *(const float4*)&As[kk][ty * 8 + 4];
            *(float4*)&bf[0] = *(const float4*)&Bs[kk][tx * 8];
            *(float4*)&bf[4] = *(const float4*)&Bs[kk][tx * 8 + 4];
#pragma unroll
            for (int i = 0; i < 8; i++)
#pragma unroll
                for (int j = 0; j < 8; j++) acc[i][j] = fmaf(af[i], bf[j], acc[i][j]);
        }
        __syncthreads();
    }

#pragma unroll
    for (int i = 0; i < 8; i++) {
        int m = m0 + ty * 8 + i;
#pragma unroll
        for (int j = 0; j < 8; j += 4) {
            int n = n0 + tx * 8 + j;
            float4 o;
            o.x = acc[i][j + 0] + bias[n + 0];
            o.y = acc[i][j + 1] + bias[n + 1];
            o.z = acc[i][j + 2] + bias[n + 2];
            o.w = acc[i][j + 3] + bias[n + 3];
            *(float4*)(g_xw + (size_t)m * G4 + n) = o;
        }
    }
}

// ---------------- persistent LSTM recurrence: fp16 weights resident in SMEM ----------------
// 147 blocks, 14 warps; warp u owns hidden unit j = blk*14+u (4 gate rows in SMEM).
// h_{t-1} is read straight from L2/L1 via __ldg (fresh address every step -> no
// staleness, no staging syncs). One grid barrier per step; no gpu-scope fences.
__global__ void __launch_bounds__(RTH, 1)
lstm_fp16_kernel(int layer)
{
    extern __shared__ unsigned char smem_raw[];
    __half* w_sm = (__half*)smem_raw;                            // RROWS*H2 halfs

    const int tid  = threadIdx.x;
    const int wu   = tid >> 5;      // warp = local unit index
    const int lane = tid & 31;
    const int j0   = blockIdx.x * UB;
    const int ub   = min(UB, H2 - j0);
    const int j    = j0 + wu;
    const bool active = (wu < ub);

    // Stage this block's weights into SMEM (coalesced uint4)
    {
        const uint4* src = (const uint4*)(g_wh16 + ((size_t)layer * G4 + (size_t)j0 * 4) * H2);
        int n = ub * 4 * H2 / 8;
        for (int i = tid; i < n; i += RTH) ((uint4*)w_sm)[i] = src[i];
    }
    __syncthreads();

    float creg = 0.f;

    for (int t = 0; t < TT; ++t) {
        // xw for this unit's 4 gates (lanes 0..3)
        float xwv = 0.f;
        if (active && lane < 4)
            xwv = __ldg(&g_xw[(size_t)t * G4 + (size_t)lane * H2 + j]);

        float a0 = 0.f, a1 = 0.f, a2 = 0.f, a3 = 0.f;
        if (t > 0 && active) {
            const float4* hb4 = (const float4*)(g_hseq + (size_t)(t - 1) * H2);
            const __half* wr  = w_sm + (size_t)(wu * 4) * H2;
#pragma unroll
            for (int k = 0; k < 16; ++k) {
                float4 hv = __ldg(hb4 + lane + 32 * k);
                int wo = k * 128 + lane * 4;
                uint2 w0 = *(const uint2*)(wr + 0 * H2 + wo);
                uint2 w1 = *(const uint2*)(wr + 1 * H2 + wo);
                uint2 w2 = *(const uint2*)(wr + 2 * H2 + wo);
                uint2 w3 = *(const uint2*)(wr + 3 * H2 + wo);
                float2 f;
                f = __half22float2(*(__half2*)&w0.x); a0 = fmaf(f.x, hv.x, a0); a0 = fmaf(f.y, hv.y, a0);
                f = __half22float2(*(__half2*)&w0.y); a0 = fmaf(f.x, hv.z, a0); a0 = fmaf(f.y, hv.w, a0);
                f = __half22float2(*(__half2*)&w1.x); a1 = fmaf(f.x, hv.x, a1); a1 = fmaf(f.y, hv.y, a1);
                f = __half22float2(*(__half2*)&w1.y); a1 = fmaf(f.x, hv.z, a1); a1 = fmaf(f.y, hv.w, a1);
                f = __half22float2(*(__half2*)&w2.x); a2 = fmaf(f.x, hv.x, a2); a2 = fmaf(f.y, hv.y, a2);
                f = __half22float2(*(__half2*)&w2.y); a2 = fmaf(f.x, hv.z, a2); a2 = fmaf(f.y, hv.w, a2);
                f = __half22float2(*(__half2*)&w3.x); a3 = fmaf(f.x, hv.x, a3); a3 = fmaf(f.y, hv.y, a3);
                f = __half22float2(*(__half2*)&w3.y); a3 = fmaf(f.x, hv.z, a3); a3 = fmaf(f.y, hv.w, a3);
            }
        }

        if (active) {
            // butterfly: every lane ends with the full sum of each gate
#pragma unroll
            for (int off = 16; off; off >>= 1) {
                a0 += __shfl_xor_sync(0xffffffffu, a0, off);
                a1 += __shfl_xor_sync(0xffffffffu, a1, off);
                a2 += __shfl_xor_sync(0xffffffffu, a2, off);
                a3 += __shfl_xor_sync(0xffffffffu, a3, off);
            }
            float pre = xwv;
            if      (lane == 0) pre += a0;
            else if (lane == 1) pre += a1;
            else if (lane == 2) pre += a2;
            else if (lane == 3) pre += a3;
            float pi_ = __shfl_sync(0xffffffffu, pre, 0);
            float pf_ = __shfl_sync(0xffffffffu, pre, 1);
            float pg_ = __shfl_sync(0xffffffffu, pre, 2);
            float po_ = __shfl_sync(0xffffffffu, pre, 3);
            if (lane == 0) {
                creg = sigf(pf_) * creg + sigf(pi_) * tanhf(pg_);
                float hval = sigf(po_) * tanhf(creg);
                g_hseq[(size_t)t * H2 + j] = hval;   // plain store; barrier publishes it
            }
        }
        grid_barrier();
    }
}

// ---------------- output: logits = h_last @ w_out^T + b_out; log_softmax ----------------
__global__ void out_kernel(const float* __restrict__ w_out, const float* __restrict__ b_out,
                           float* __restrict__ out)
{
    __shared__ float red[16];
    const float* h = g_hseq + (size_t)(TT - 1) * H2;
    int tid = threadIdx.x, wid = tid >> 5, lane = tid & 31;
    float s0 = 0.f, s1 = 0.f;
    for (int k = tid; k < H2; k += 256) {
        float hv = h[k];
        s0 = fmaf(hv, w_out[k], s0);
        s1 = fmaf(hv, w_out[H2 + k], s1);
    }
#pragma unroll
    for (int o = 16; o > 0; o >>= 1) {
        s0 += __shfl_down_sync(0xffffffffu, s0, o);
        s1 += __shfl_down_sync(0xffffffffu, s1, o);
    }
    if (lane == 0) { red[wid] = s0; red[8 + wid] = s1; }
    __syncthreads();
    if (tid == 0) {
        float l0 = b_out[0], l1 = b_out[1];
        for (int w = 0; w < 8; w++) { l0 += red[w]; l1 += red[8 + w]; }
        float m = fmaxf(l0, l1);
        float z = logf(expf(l0 - m) + expf(l1 - m));
        out[0] = (l0 - m) - z;
        out[1] = (l1 - m) - z;
    }
}

// ---------------- host ----------------
extern "C" void kernel_launch(void* const* d_in, const int* in_sizes, int n_in,
                              void* d_out, int out_size)
{
    const float *event = nullptr, *w_ih0 = nullptr, *w_ih = nullptr, *whh = nullptr;
    const float *b_ih = nullptr, *b_hh = nullptr, *w_out = nullptr, *b_out = nullptr;
    for (int i = 0; i < n_in; i++) {
        long long s = in_sizes[i];
        const float* p = (const float*)d_in[i];
        if      (s == 2048)              event = p;
        else if (s == 8192)              w_ih0 = p;
        else if (s == 50331648LL)        w_ih  = p;   // 3*8192*2048
        else if (s == 67108864LL)        whh   = p;   // 4*8192*2048
        else if (s == 32768)             { if (!b_ih) b_ih = p; else b_hh = p; }
        else if (s == 4096)              w_out = p;
        else if (s == 2)                 b_out = p;
    }

    cudaFuncSetAttribute(lstm_fp16_kernel,
                         cudaFuncAttributeMaxDynamicSharedMemorySize, SMEM_DYN);

    bias_kernel<<<(LAYERS * G4 + 255) / 256, 256>>>(b_ih, b_hh);
    convert_whh_kernel<<<LAYERS * G4, 512>>>(whh);
    xw0_kernel<<<TT, 256>>>(event, w_ih0);
    lstm_fp16_kernel<<<NB, RTH, SMEM_DYN>>>(0);

    for (int l = 1; l < LAYERS; l++) {
        xw_gemm_kernel<<<dim3(G4 / 128, TT / 128), 256>>>(w_ih + (size_t)(l - 1) * G4 * H2, l);
        lstm_fp16_kernel<<<NB, RTH, SMEM_DYN>>>(l);
    }

    out_kernel<<<1, 256>>>(w_out, b_out, (float*)d_out);
}

// round 10
// speedup vs baseline: 1.7042x; 1.2159x over previous
#include <cuda_runtime.h>
#include <cuda_fp16.h>
#include <mma.h>
#include <math.h>

using namespace nvcuda;

#define TT      2048
#define H2      2048
#define G4      8192      // 4 * H2 gate rows
#define LAYERS  4

// ---- persistent fp16-SMEM recurrence config ----
#define UB      14                      // hidden units per block
#define NB      ((H2 + UB - 1) / UB)    // 147 blocks (co-resident, 1/SM)
#define RROWS   (UB * 4)                // 56 gate rows per block
#define RTH     896                     // 28 warps: warp pair (u,p) per unit
#define SMEM_W   (RROWS * H2 * 2)       // 229376 B fp16 weights
#define SMEM_DYN (SMEM_W + UB * 16)     // + partial float4 per unit

// ---------------- device scratch (static: no allocation anywhere) ----------------
__device__ float  g_xw[(size_t)TT * G4];            // 64 MB: raw xw (no bias)
__device__ float  g_hseq[(size_t)TT * H2];          // 16 MB: h fp32 (recurrence + out)
__device__ __half g_h16[(size_t)TT * H2];           // 8 MB:  h fp16 (GEMM A)
__device__ float  g_bias[LAYERS * G4];              // b_ih + b_hh
__device__ __half g_wh16[(size_t)LAYERS * G4 * H2]; // 128 MB: W_hh fp16, unit-major rows
__device__ __half g_wih16[(size_t)(LAYERS - 1) * G4 * H2]; // 96 MB: w_ih fp16 (k-major rows)
__device__ unsigned int g_bar_count = 0;
__device__ unsigned int g_bar_epoch = 0;

// ---------------- grid barrier: acq_rel arrive + release epoch + acquire poll ------
__device__ __forceinline__ void grid_barrier()
{
    __syncthreads();
    if (threadIdx.x == 0) {
        unsigned e;
        asm volatile("ld.relaxed.gpu.u32 %0, [%1];" : "=r"(e) : "l"(&g_bar_epoch));
        unsigned a;
        asm volatile("atom.acq_rel.gpu.add.u32 %0, [%1], %2;"
                     : "=r"(a) : "l"(&g_bar_count), "r"(1u) : "memory");
        if (a == NB - 1) {
            asm volatile("st.relaxed.gpu.u32 [%0], %1;" :: "l"(&g_bar_count), "r"(0u) : "memory");
            asm volatile("red.release.gpu.add.u32 [%0], %1;" :: "l"(&g_bar_epoch), "r"(1u) : "memory");
        } else {
            unsigned cur;
            do {
                asm volatile("ld.acquire.gpu.u32 %0, [%1];" : "=r"(cur) : "l"(&g_bar_epoch) : "memory");
            } while (cur == e);
        }
    }
    __syncthreads();
}

__device__ __forceinline__ float fsig(float x) { return __fdividef(1.f, 1.f + __expf(-x)); }
__device__ __forceinline__ float ftanh(float x) { return __fdividef(2.f, 1.f + __expf(-2.f * x)) - 1.f; }

// ---------------- bias precompute ----------------
__global__ void bias_kernel(const float* __restrict__ b_ih, const float* __restrict__ b_hh)
{
    int i = blockIdx.x * blockDim.x + threadIdx.x;
    if (i < LAYERS * G4) g_bias[i] = b_ih[i] + b_hh[i];
}

// ---------------- convert W_hh fp32 -> fp16, reorder rows to unit-major (j*4+g) ----
__global__ void convert_whh_kernel(const float* __restrict__ whh)
{
    int row   = blockIdx.x;
    int layer = row >> 13;
    int r     = row & 8191;
    int j     = r >> 2, g = r & 3;
    const float* src = whh + ((size_t)layer * G4 + (size_t)g * H2 + j) * H2;
    __half2* dst = (__half2*)(g_wh16 + (size_t)row * H2);
    int i = threadIdx.x * 4;
    float4 v = *(const float4*)(src + i);
    dst[threadIdx.x * 2 + 0] = __floats2half2_rn(v.x, v.y);
    dst[threadIdx.x * 2 + 1] = __floats2half2_rn(v.z, v.w);
}

// ---------------- convert w_ih fp32 -> fp16 (layout preserved) ----------------
__global__ void convert_wih_kernel(const float* __restrict__ wih)
{
    size_t row = blockIdx.x;
    const float* src = wih + row * H2;
    __half2* dst = (__half2*)(g_wih16 + row * H2);
    int i = threadIdx.x * 4;
    float4 v = *(const float4*)(src + i);
    dst[threadIdx.x * 2 + 0] = __floats2half2_rn(v.x, v.y);
    dst[threadIdx.x * 2 + 1] = __floats2half2_rn(v.z, v.w);
}

// ---------------- layer-0 xw (raw, no bias): xw[t][r] = event[t]*w_ih0[r] ---------
__global__ void xw0_kernel(const float* __restrict__ event, const float* __restrict__ w_ih0)
{
    int t = blockIdx.x;
    float e = event[t];
    float4* dst = (float4*)(g_xw + (size_t)t * G4);
    const float4* w4 = (const float4*)w_ih0;
    for (int i = threadIdx.x; i < G4 / 4; i += blockDim.x) {
        float4 w = w4[i];
        dst[i] = make_float4(e * w.x, e * w.y, e * w.z, e * w.w);
    }
}

// ---------------- tensor-core xw GEMM: xw = h16 @ w_ih16^T (raw, no bias) ---------
// C[M=2048(t)][N=8192(r)] = A[M][K=2048] * B[N][K]^T, fp16 in / fp32 acc.
// 128x128x32 tile, 8 warps (2x4), wmma 16x16x16, SMEM pad to 48 halves/row.
#define GLD 48
__global__ void __launch_bounds__(256)
xw_gemm16_kernel(const __half* __restrict__ B)
{
    __shared__ __half As[128 * GLD];
    __shared__ __half Bs[128 * GLD];
    const __half* A = g_h16;
    const int tid = threadIdx.x;
    const int wid = tid >> 5;
    const int wm = wid >> 2, wn = wid & 3;
    const int m0 = blockIdx.y * 128, n0 = blockIdx.x * 128;

    const int row0 = tid >> 2,        q0 = tid & 3;          // idx = tid
    const int row1 = (tid + 256) >> 2, q1 = (tid + 256) & 3; // idx = tid+256

    wmma::fragment<wmma::accumulator, 16, 16, 16, float> acc[4][2];
#pragma unroll
    for (int i = 0; i < 4; i++)
#pragma unroll
        for (int j = 0; j < 2; j++) wmma::fill_fragment(acc[i][j], 0.f);

    uint4 pa0, pa1, pb0, pb1;
    pa0 = *(const uint4*)(A + (size_t)(m0 + row0) * H2 + 0 + q0 * 8);
    pa1 = *(const uint4*)(A + (size_t)(m0 + row1) * H2 + 0 + q1 * 8);
    pb0 = *(const uint4*)(B + (size_t)(n0 + row0) * H2 + 0 + q0 * 8);
    pb1 = *(const uint4*)(B + (size_t)(n0 + row1) * H2 + 0 + q1 * 8);

    for (int k0 = 0; k0 < H2; k0 += 32) {
        *(uint4*)(As + row0 * GLD + q0 * 8) = pa0;
        *(uint4*)(As + row1 * GLD + q1 * 8) = pa1;
        *(uint4*)(Bs + row0 * GLD + q0 * 8) = pb0;
        *(uint4*)(Bs + row1 * GLD + q1 * 8) = pb1;
        __syncthreads();

        int kn = k0 + 32;
        if (kn < H2) {
            pa0 = *(const uint4*)(A + (size_t)(m0 + row0) * H2 + kn + q0 * 8);
            pa1 = *(const uint4*)(A + (size_t)(m0 + row1) * H2 + kn + q1 * 8);
            pb0 = *(const uint4*)(B + (size_t)(n0 + row0) * H2 + kn + q0 * 8);
            pb1 = *(const uint4*)(B + (size_t)(n0 + row1) * H2 + kn + q1 * 8);
        }

#pragma unroll
        for (int kk = 0; kk < 2; kk++) {
            wmma::fragment<wmma::matrix_a, 16, 16, 16, __half, wmma::row_major> af[4];
            wmma::fragment<wmma::matrix_b, 16, 16, 16, __half, wmma::col_major> bf[2];
#pragma unroll
            for (int mi = 0; mi < 4; mi++)
                wmma::load_matrix_sync(af[mi], As + (wm * 64 + mi * 16) * GLD + kk * 16, GLD);
#pragma unroll
            for (int ni = 0; ni < 2; ni++)
                wmma::load_matrix_sync(bf[ni], Bs + (wn * 32 + ni * 16) * GLD + kk * 16, GLD);
#pragma unroll
            for (int mi = 0; mi < 4; mi++)
#pragma unroll
                for (int ni = 0; ni < 2; ni++)
                    wmma::mma_sync(acc[mi][ni], af[mi], bf[ni], acc[mi][ni]);
        }
        __syncthreads();
    }

#pragma unroll
    for (int mi = 0; mi < 4; mi++)
#pragma unroll
        for (int ni = 0; ni < 2; ni++)
            wmma::store_matrix_sync(
                g_xw + (size_t)(m0 + wm * 64 + mi * 16) * G4 + n0 + wn * 32 + ni * 16,
                acc[mi][ni], G4, wmma::mem_row_major);
}

// ---------------- persistent LSTM recurrence: 28 warps, warp-pair per unit --------
// Warp w: u = w>>1 (unit), p = w&1 (k-half). Each warp: 4 gate rows x 1024 k.
// Partner halves combine via a float4 SMEM slot; p0-lane0 does the cell update.
__global__ void __launch_bounds__(RTH, 1)
lstm_fp16_kernel(int layer)
{
    extern __shared__ unsigned char smem_raw[];
    __half* w_sm = (__half*)smem_raw;                         // RROWS*H2 halfs
    float4* part = (float4*)(smem_raw + SMEM_W);              // UB slots

    const int tid  = threadIdx.x;
    const int w    = tid >> 5;
    const int lane = tid & 31;
    const int u    = w >> 1;        // local unit
    const int p    = w & 1;         // k-half
    const int j0   = blockIdx.x * UB;
    const int ub   = min(UB, H2 - j0);
    const int j    = j0 + u;
    const bool active = (u < ub);
    const bool leader = active && p == 0 && lane == 0;

    // Stage this block's weights into SMEM (coalesced uint4)
    {
        const uint4* src = (const uint4*)(g_wh16 + ((size_t)layer * G4 + (size_t)j0 * 4) * H2);
        int n = ub * 4 * H2 / 8;
        for (int i = tid; i < n; i += RTH) ((uint4*)w_sm)[i] = src[i];
    }

    // Per-unit bias (4 gates) in leader registers
    float bi = 0.f, bf_ = 0.f, bg = 0.f, bo = 0.f;
    if (leader) {
        const float* bb = g_bias + (size_t)layer * G4;
        bi  = bb[0 * H2 + j];
        bf_ = bb[1 * H2 + j];
        bg  = bb[2 * H2 + j];
        bo  = bb[3 * H2 + j];
    }
    __syncthreads();

    float creg = 0.f;

    for (int t = 0; t < TT; ++t) {
        // leader prefetches xw for the 4 gates (independent of barrier)
        float xi = 0.f, xf = 0.f, xg = 0.f, xo = 0.f;
        if (leader) {
            const float* xr = g_xw + (size_t)t * G4;
            xi = __ldg(xr + 0 * H2 + j);
            xf = __ldg(xr + 1 * H2 + j);
            xg = __ldg(xr + 2 * H2 + j);
            xo = __ldg(xr + 3 * H2 + j);
        }

        float a0 = 0.f, a1 = 0.f, a2 = 0.f, a3 = 0.f;
        if (t > 0 && active) {
            const float4* hb4 = (const float4*)(g_hseq + (size_t)(t - 1) * H2) + p * 256;
            const __half* wr  = w_sm + (size_t)(u * 4) * H2 + p * 1024;
#pragma unroll
            for (int k = 0; k < 8; ++k) {
                float4 hv = __ldg(hb4 + lane + 32 * k);
                int wo = k * 128 + lane * 4;
                uint2 w0 = *(const uint2*)(wr + 0 * H2 + wo);
                uint2 w1 = *(const uint2*)(wr + 1 * H2 + wo);
                uint2 w2 = *(const uint2*)(wr + 2 * H2 + wo);
                uint2 w3 = *(const uint2*)(wr + 3 * H2 + wo);
                float2 f;
                f = __half22float2(*(__half2*)&w0.x); a0 = fmaf(f.x, hv.x, a0); a0 = fmaf(f.y, hv.y, a0);
                f = __half22float2(*(__half2*)&w0.y); a0 = fmaf(f.x, hv.z, a0); a0 = fmaf(f.y, hv.w, a0);
                f = __half22float2(*(__half2*)&w1.x); a1 = fmaf(f.x, hv.x, a1); a1 = fmaf(f.y, hv.y, a1);
                f = __half22float2(*(__half2*)&w1.y); a1 = fmaf(f.x, hv.z, a1); a1 = fmaf(f.y, hv.w, a1);
                f = __half22float2(*(__half2*)&w2.x); a2 = fmaf(f.x, hv.x, a2); a2 = fmaf(f.y, hv.y, a2);
                f = __half22float2(*(__half2*)&w2.y); a2 = fmaf(f.x, hv.z, a2); a2 = fmaf(f.y, hv.w, a2);
                f = __half22float2(*(__half2*)&w3.x); a3 = fmaf(f.x, hv.x, a3); a3 = fmaf(f.y, hv.y, a3);
                f = __half22float2(*(__half2*)&w3.y); a3 = fmaf(f.x, hv.z, a3); a3 = fmaf(f.y, hv.w, a3);
            }
        }

        // warp-level reduce (each lane ends with full per-half sums)
#pragma unroll
        for (int off = 16; off; off >>= 1) {
            a0 += __shfl_xor_sync(0xffffffffu, a0, off);
            a1 += __shfl_xor_sync(0xffffffffu, a1, off);
            a2 += __shfl_xor_sync(0xffffffffu, a2, off);
            a3 += __shfl_xor_sync(0xffffffffu, a3, off);
        }
        if (active && p == 1 && lane == 0)
            part[u] = make_float4(a0, a1, a2, a3);
        __syncthreads();

        if (leader) {
            float4 q = part[u];
            float pi_ = a0 + q.x + xi + bi;
            float pf2 = a1 + q.y + xf + bf_;
            float pg_ = a2 + q.z + xg + bg;
            float po_ = a3 + q.w + xo + bo;
            creg = fsig(pf2) * creg + fsig(pi_) * ftanh(pg_);
            float hval = fsig(po_) * ftanh(creg);
            g_hseq[(size_t)t * H2 + j] = hval;           // fp32 for recurrence/out
            g_h16[(size_t)t * H2 + j]  = __float2half_rn(hval); // fp16 for next GEMM
        }
        grid_barrier();
    }
}

// ---------------- output: logits = h_last @ w_out^T + b_out; log_softmax ----------------
__global__ void out_kernel(const float* __restrict__ w_out, const float* __restrict__ b_out,
                           float* __restrict__ out)
{
    __shared__ float red[16];
    const float* h = g_hseq + (size_t)(TT - 1) * H2;
    int tid = threadIdx.x, wid = tid >> 5, lane = tid & 31;
    float s0 = 0.f, s1 = 0.f;
    for (int k = tid; k < H2; k += 256) {
        float hv = h[k];
        s0 = fmaf(hv, w_out[k], s0);
        s1 = fmaf(hv, w_out[H2 + k], s1);
    }
#pragma unroll
    for (int o = 16; o > 0; o >>= 1) {
        s0 += __shfl_down_sync(0xffffffffu, s0, o);
        s1 += __shfl_down_sync(0xffffffffu, s1, o);
    }
    if (lane == 0) { red[wid] = s0; red[8 + wid] = s1; }
    __syncthreads();
    if (tid == 0) {
        float l0 = b_out[0], l1 = b_out[1];
        for (int w = 0; w < 8; w++) { l0 += red[w]; l1 += red[8 + w]; }
        float m = fmaxf(l0, l1);
        float z = logf(expf(l0 - m) + expf(l1 - m));
        out[0] = (l0 - m) - z;
        out[1] = (l1 - m) - z;
    }
}

// ---------------- host ----------------
extern "C" void kernel_launch(void* const* d_in, const int* in_sizes, int n_in,
                              void* d_out, int out_size)
{
    const float *event = nullptr, *w_ih0 = nullptr, *w_ih = nullptr, *whh = nullptr;
    const float *b_ih = nullptr, *b_hh = nullptr, *w_out = nullptr, *b_out = nullptr;
    for (int i = 0; i < n_in; i++) {
        long long s = in_sizes[i];
        const float* p = (const float*)d_in[i];
        if      (s == 2048)              event = p;
        else if (s == 8192)              w_ih0 = p;
        else if (s == 50331648LL)        w_ih  = p;   // 3*8192*2048
        else if (s == 67108864LL)        whh   = p;   // 4*8192*2048
        else if (s == 32768)             { if (!b_ih) b_ih = p; else b_hh = p; }
        else if (s == 4096)              w_out = p;
        else if (s == 2)                 b_out = p;
    }

    cudaFuncSetAttribute(lstm_fp16_kernel,
                         cudaFuncAttributeMaxDynamicSharedMemorySize, SMEM_DYN);

    bias_kernel<<<(LAYERS * G4 + 255) / 256, 256>>>(b_ih, b_hh);
    convert_whh_kernel<<<LAYERS * G4, 512>>>(whh);
    convert_wih_kernel<<<(LAYERS - 1) * G4, 512>>>(w_ih);
    xw0_kernel<<<TT, 256>>>(event, w_ih0);
    lstm_fp16_kernel<<<NB, RTH, SMEM_DYN>>>(0);

    for (int l = 1; l < LAYERS; l++) {
        __half* wb = nullptr;
        cudaGetSymbolAddress((void**)&wb, g_wih16);    // address-of, not allocation
        xw_gemm16_kernel<<<dim3(G4 / 128, TT / 128), 256>>>(wb + (size_t)(l - 1) * G4 * H2);
        lstm_fp16_kernel<<<NB, RTH, SMEM_DYN>>>(l);
    }

    out_kernel<<<1, 256>>>(w_out, b_out, (float*)d_out);
}

// round 12
// speedup vs baseline: 1.7049x; 1.0004x over previous
#include <cuda_runtime.h>
#include <cuda_fp16.h>
#include <mma.h>
#include <math.h>

using namespace nvcuda;

#define TT      2048
#define H2      2048
#define G4      8192      // 4 * H2 gate rows
#define LAYERS  4

// ---- persistent fp16-SMEM recurrence config ----
#define UB      14                      // hidden units per block
#define NB      ((H2 + UB - 1) / UB)    // 147 blocks (co-resident, 1/SM)
#define RROWS   (UB * 4)                // 56 gate rows per block
#define RTH     896                     // 28 warps: warp pair (u,p) per unit
#define SMEM_W   (RROWS * H2 * 2)       // 229376 B fp16 weights
#define SMEM_DYN (SMEM_W + UB * 16)     // + partial float4 per unit

// ---------------- device scratch (static: no allocation anywhere) ----------------
__device__ float  g_xw[(size_t)TT * G4];            // 64 MB: raw xw (no bias)
__device__ float  g_hseq[(size_t)TT * H2];          // 16 MB: h fp32
__device__ __half g_h16[(size_t)TT * H2];           // 8 MB:  h fp16 (GEMM A)
__device__ float  g_bias[LAYERS * G4];              // b_ih + b_hh
__device__ __half g_wh16[(size_t)LAYERS * G4 * H2]; // 128 MB: W_hh fp16, unit-major rows
__device__ __half g_wih16[(size_t)(LAYERS - 1) * G4 * H2]; // 96 MB: w_ih fp16
__device__ unsigned int g_bar_count = 0;
__device__ unsigned int g_bar_epoch = 0;            // monotone (replay-invariant)

__device__ __forceinline__ float fsig(float x) { return __fdividef(1.f, 1.f + __expf(-x)); }
__device__ __forceinline__ float ftanh(float x) { return __fdividef(2.f, 1.f + __expf(-2.f * x)) - 1.f; }

// ---------------- bias precompute ----------------
__global__ void bias_kernel(const float* __restrict__ b_ih, const float* __restrict__ b_hh)
{
    int i = blockIdx.x * blockDim.x + threadIdx.x;
    if (i < LAYERS * G4) g_bias[i] = b_ih[i] + b_hh[i];
}

// ---------------- convert W_hh fp32 -> fp16, reorder rows to unit-major (j*4+g) ----
__global__ void convert_whh_kernel(const float* __restrict__ whh)
{
    int row   = blockIdx.x;
    int layer = row >> 13;
    int r     = row & 8191;
    int j     = r >> 2, g = r & 3;
    const float* src = whh + ((size_t)layer * G4 + (size_t)g * H2 + j) * H2;
    __half2* dst = (__half2*)(g_wh16 + (size_t)row * H2);
    int i = threadIdx.x * 4;
    float4 v = *(const float4*)(src + i);
    dst[threadIdx.x * 2 + 0] = __floats2half2_rn(v.x, v.y);
    dst[threadIdx.x * 2 + 1] = __floats2half2_rn(v.z, v.w);
}

// ---------------- convert w_ih fp32 -> fp16 (layout preserved) ----------------
__global__ void convert_wih_kernel(const float* __restrict__ wih)
{
    size_t row = blockIdx.x;
    const float* src = wih + row * H2;
    __half2* dst = (__half2*)(g_wih16 + row * H2);
    int i = threadIdx.x * 4;
    float4 v = *(const float4*)(src + i);
    dst[threadIdx.x * 2 + 0] = __floats2half2_rn(v.x, v.y);
    dst[threadIdx.x * 2 + 1] = __floats2half2_rn(v.z, v.w);
}

// ---------------- layer-0 xw (raw, no bias) ----------------
__global__ void xw0_kernel(const float* __restrict__ event, const float* __restrict__ w_ih0)
{
    int t = blockIdx.x;
    float e = event[t];
    float4* dst = (float4*)(g_xw + (size_t)t * G4);
    const float4* w4 = (const float4*)w_ih0;
    for (int i = threadIdx.x; i < G4 / 4; i += blockDim.x) {
        float4 w = w4[i];
        dst[i] = make_float4(e * w.x, e * w.y, e * w.z, e * w.w);
    }
}

// ---------------- tensor-core xw GEMM: xw = h16 @ w_ih16^T (raw, no bias) ---------
#define GLD 48
__global__ void __launch_bounds__(256)
xw_gemm16_kernel(const __half* __restrict__ B)
{
    __shared__ __half As[128 * GLD];
    __shared__ __half Bs[128 * GLD];
    const __half* A = g_h16;
    const int tid = threadIdx.x;
    const int wid = tid >> 5;
    const int wm = wid >> 2, wn = wid & 3;
    const int m0 = blockIdx.y * 128, n0 = blockIdx.x * 128;

    const int row0 = tid >> 2,         q0 = tid & 3;
    const int row1 = (tid + 256) >> 2, q1 = (tid + 256) & 3;

    wmma::fragment<wmma::accumulator, 16, 16, 16, float> acc[4][2];
#pragma unroll
    for (int i = 0; i < 4; i++)
#pragma unroll
        for (int j = 0; j < 2; j++) wmma::fill_fragment(acc[i][j], 0.f);

    uint4 pa0, pa1, pb0, pb1;
    pa0 = *(const uint4*)(A + (size_t)(m0 + row0) * H2 + 0 + q0 * 8);
    pa1 = *(const uint4*)(A + (size_t)(m0 + row1) * H2 + 0 + q1 * 8);
    pb0 = *(const uint4*)(B + (size_t)(n0 + row0) * H2 + 0 + q0 * 8);
    pb1 = *(const uint4*)(B + (size_t)(n0 + row1) * H2 + 0 + q1 * 8);

    for (int k0 = 0; k0 < H2; k0 += 32) {
        *(uint4*)(As + row0 * GLD + q0 * 8) = pa0;
        *(uint4*)(As + row1 * GLD + q1 * 8) = pa1;
        *(uint4*)(Bs + row0 * GLD + q0 * 8) = pb0;
        *(uint4*)(Bs + row1 * GLD + q1 * 8) = pb1;
        __syncthreads();

        int kn = k0 + 32;
        if (kn < H2) {
            pa0 = *(const uint4*)(A + (size_t)(m0 + row0) * H2 + kn + q0 * 8);
            pa1 = *(const uint4*)(A + (size_t)(m0 + row1) * H2 + kn + q1 * 8);
            pb0 = *(const uint4*)(B + (size_t)(n0 + row0) * H2 + kn + q0 * 8);
            pb1 = *(const uint4*)(B + (size_t)(n0 + row1) * H2 + kn + q1 * 8);
        }

#pragma unroll
        for (int kk = 0; kk < 2; kk++) {
            wmma::fragment<wmma::matrix_a, 16, 16, 16, __half, wmma::row_major> af[4];
            wmma::fragment<wmma::matrix_b, 16, 16, 16, __half, wmma::col_major> bf[2];
#pragma unroll
            for (int mi = 0; mi < 4; mi++)
                wmma::load_matrix_sync(af[mi], As + (wm * 64 + mi * 16) * GLD + kk * 16, GLD);
#pragma unroll
            for (int ni = 0; ni < 2; ni++)
                wmma::load_matrix_sync(bf[ni], Bs + (wn * 32 + ni * 16) * GLD + kk * 16, GLD);
#pragma unroll
            for (int mi = 0; mi < 4; mi++)
#pragma unroll
                for (int ni = 0; ni < 2; ni++)
                    wmma::mma_sync(acc[mi][ni], af[mi], bf[ni], acc[mi][ni]);
        }
        __syncthreads();
    }

#pragma unroll
    for (int mi = 0; mi < 4; mi++)
#pragma unroll
        for (int ni = 0; ni < 2; ni++)
            wmma::store_matrix_sync(
                g_xw + (size_t)(m0 + wm * 64 + mi * 16) * G4 + n0 + wn * 32 + ni * 16,
                acc[mi][ni], G4, wmma::mem_row_major);
}

// ---------------- persistent LSTM recurrence ----------------
// 28 warps: warp w -> (u = w>>1, p = w&1). Pair combines via SMEM + named barrier
// (id 1+u, 64 threads). Leader (p0,lane0) updates the cell, stores h, prefetches
// xw(t+1) under the barrier wait. Grid barrier: R10-proven arrive/release/poll.
__global__ void __launch_bounds__(RTH, 1)
lstm_fp16_kernel(int layer)
{
    extern __shared__ unsigned char smem_raw[];
    __half* w_sm = (__half*)smem_raw;                         // RROWS*H2 halfs
    float4* part = (float4*)(smem_raw + SMEM_W);              // UB slots

    const int tid  = threadIdx.x;
    const int w    = tid >> 5;
    const int lane = tid & 31;
    const int u    = w >> 1;        // local unit
    const int p    = w & 1;         // k-half
    const int j0   = blockIdx.x * UB;
    const int ub   = min(UB, H2 - j0);
    const int j    = j0 + u;
    const bool active = (u < ub);
    const bool leader = active && p == 0 && lane == 0;

    // Stage this block's weights into SMEM (coalesced uint4)
    {
        const uint4* src = (const uint4*)(g_wh16 + ((size_t)layer * G4 + (size_t)j0 * 4) * H2);
        int n = ub * 4 * H2 / 8;
        for (int i = tid; i < n; i += RTH) ((uint4*)w_sm)[i] = src[i];
    }

    // Leader: bias + xw(t=0) prefetch
    float bi = 0.f, bf_ = 0.f, bg = 0.f, bo = 0.f;
    float xi = 0.f, xf = 0.f, xg = 0.f, xo = 0.f;
    if (leader) {
        const float* bb = g_bias + (size_t)layer * G4;
        bi  = bb[0 * H2 + j];
        bf_ = bb[1 * H2 + j];
        bg  = bb[2 * H2 + j];
        bo  = bb[3 * H2 + j];
        const float* xr = g_xw;
        xi = __ldg(xr + 0 * H2 + j);
        xf = __ldg(xr + 1 * H2 + j);
        xg = __ldg(xr + 2 * H2 + j);
        xo = __ldg(xr + 3 * H2 + j);
    }
    __syncthreads();

    float creg = 0.f;

    for (int t = 0; t < TT; ++t) {
        float a0 = 0.f, a1 = 0.f, a2 = 0.f, a3 = 0.f;
        if (t > 0 && active) {
            const float4* hb4 = (const float4*)(g_hseq + (size_t)(t - 1) * H2) + p * 256;
            const __half* wr  = w_sm + (size_t)(u * 4) * H2 + p * 1024;
#pragma unroll
            for (int i = 0; i < 4; ++i) {
                const int off = i * 256 + lane * 8;           // halfs / floats
                float4 h0 = __ldg(hb4 + (off >> 2));
                float4 h1 = __ldg(hb4 + (off >> 2) + 1);
                uint4 w0 = *(const uint4*)(wr + 0 * H2 + off);
                uint4 w1 = *(const uint4*)(wr + 1 * H2 + off);
                uint4 w2 = *(const uint4*)(wr + 2 * H2 + off);
                uint4 w3 = *(const uint4*)(wr + 3 * H2 + off);
                float2 f;
                f = __half22float2(*(__half2*)&w0.x); a0 = fmaf(f.x, h0.x, a0); a0 = fmaf(f.y, h0.y, a0);
                f = __half22float2(*(__half2*)&w0.y); a0 = fmaf(f.x, h0.z, a0); a0 = fmaf(f.y, h0.w, a0);
                f = __half22float2(*(__half2*)&w0.z); a0 = fmaf(f.x, h1.x, a0); a0 = fmaf(f.y, h1.y, a0);
                f = __half22float2(*(__half2*)&w0.w); a0 = fmaf(f.x, h1.z, a0); a0 = fmaf(f.y, h1.w, a0);
                f = __half22float2(*(__half2*)&w1.x); a1 = fmaf(f.x, h0.x, a1); a1 = fmaf(f.y, h0.y, a1);
                f = __half22float2(*(__half2*)&w1.y); a1 = fmaf(f.x, h0.z, a1); a1 = fmaf(f.y, h0.w, a1);
                f = __half22float2(*(__half2*)&w1.z); a1 = fmaf(f.x, h1.x, a1); a1 = fmaf(f.y, h1.y, a1);
                f = __half22float2(*(__half2*)&w1.w); a1 = fmaf(f.x, h1.z, a1); a1 = fmaf(f.y, h1.w, a1);
                f = __half22float2(*(__half2*)&w2.x); a2 = fmaf(f.x, h0.x, a2); a2 = fmaf(f.y, h0.y, a2);
                f = __half22float2(*(__half2*)&w2.y); a2 = fmaf(f.x, h0.z, a2); a2 = fmaf(f.y, h0.w, a2);
                f = __half22float2(*(__half2*)&w2.z); a2 = fmaf(f.x, h1.x, a2); a2 = fmaf(f.y, h1.y, a2);
                f = __half22float2(*(__half2*)&w2.w); a2 = fmaf(f.x, h1.z, a2); a2 = fmaf(f.y, h1.w, a2);
                f = __half22float2(*(__half2*)&w3.x); a3 = fmaf(f.x, h0.x, a3); a3 = fmaf(f.y, h0.y, a3);
                f = __half22float2(*(__half2*)&w3.y); a3 = fmaf(f.x, h0.z, a3); a3 = fmaf(f.y, h0.w, a3);
                f = __half22float2(*(__half2*)&w3.z); a3 = fmaf(f.x, h1.x, a3); a3 = fmaf(f.y, h1.y, a3);
                f = __half22float2(*(__half2*)&w3.w); a3 = fmaf(f.x, h1.z, a3); a3 = fmaf(f.y, h1.w, a3);
            }
        }

        if (active) {
#pragma unroll
            for (int off = 16; off; off >>= 1) {
                a0 += __shfl_xor_sync(0xffffffffu, a0, off);
                a1 += __shfl_xor_sync(0xffffffffu, a1, off);
                a2 += __shfl_xor_sync(0xffffffffu, a2, off);
                a3 += __shfl_xor_sync(0xffffffffu, a3, off);
            }
            if (p == 1 && lane == 0)
                part[u] = make_float4(a0, a1, a2, a3);
            // pair-local barrier: warps 2u and 2u+1 only (64 threads)
            asm volatile("bar.sync %0, %1;" :: "r"(1 + u), "r"(64) : "memory");
        }

        if (leader) {
            float4 q = part[u];
            float pi_ = a0 + q.x + xi + bi;
            float pf2 = a1 + q.y + xf + bf_;
            float pg_ = a2 + q.z + xg + bg;
            float po_ = a3 + q.w + xo + bo;
            creg = fsig(pf2) * creg + fsig(pi_) * ftanh(pg_);
            float hval = fsig(po_) * ftanh(creg);
            g_hseq[(size_t)t * H2 + j] = hval;
            g_h16[(size_t)t * H2 + j]  = __float2half_rn(hval);
            if (t + 1 < TT) {           // prefetch xw(t+1) under the barrier wait
                const float* xr = g_xw + (size_t)(t + 1) * G4;
                xi = __ldg(xr + 0 * H2 + j);
                xf = __ldg(xr + 1 * H2 + j);
                xg = __ldg(xr + 2 * H2 + j);
                xo = __ldg(xr + 3 * H2 + j);
            }
        }

        // ---- grid barrier (R10-proven: arrive acq_rel, reset+release, acquire poll) ----
        __syncthreads();
        if (tid == 0) {
            unsigned e;
            asm volatile("ld.relaxed.gpu.u32 %0, [%1];" : "=r"(e) : "l"(&g_bar_epoch));
            unsigned a;
            asm volatile("atom.acq_rel.gpu.add.u32 %0, [%1], %2;"
                         : "=r"(a) : "l"(&g_bar_count), "r"(1u) : "memory");
            if (a == NB - 1) {
                asm volatile("st.relaxed.gpu.u32 [%0], %1;" :: "l"(&g_bar_count), "r"(0u) : "memory");
                asm volatile("red.release.gpu.add.u32 [%0], %1;" :: "l"(&g_bar_epoch), "r"(1u) : "memory");
            } else {
                unsigned cur;
                do {
                    asm volatile("ld.acquire.gpu.u32 %0, [%1];" : "=r"(cur) : "l"(&g_bar_epoch) : "memory");
                } while (cur == e);
            }
        }
        __syncthreads();
    }
}

// ---------------- output: logits = h_last @ w_out^T + b_out; log_softmax ----------------
__global__ void out_kernel(const float* __restrict__ w_out, const float* __restrict__ b_out,
                           float* __restrict__ out)
{
    __shared__ float red[16];
    const float* h = g_hseq + (size_t)(TT - 1) * H2;
    int tid = threadIdx.x, wid = tid >> 5, lane = tid & 31;
    float s0 = 0.f, s1 = 0.f;
    for (int k = tid; k < H2; k += 256) {
        float hv = h[k];
        s0 = fmaf(hv, w_out[k], s0);
        s1 = fmaf(hv, w_out[H2 + k], s1);
    }
#pragma unroll
    for (int o = 16; o > 0; o >>= 1) {
        s0 += __shfl_down_sync(0xffffffffu, s0, o);
        s1 += __shfl_down_sync(0xffffffffu, s1, o);
    }
    if (lane == 0) { red[wid] = s0; red[8 + wid] = s1; }
    __syncthreads();
    if (tid == 0) {
        float l0 = b_out[0], l1 = b_out[1];
        for (int w = 0; w < 8; w++) { l0 += red[w]; l1 += red[8 + w]; }
        float m = fmaxf(l0, l1);
        float z = logf(expf(l0 - m) + expf(l1 - m));
        out[0] = (l0 - m) - z;
        out[1] = (l1 - m) - z;
    }
}

// ---------------- host ----------------
extern "C" void kernel_launch(void* const* d_in, const int* in_sizes, int n_in,
                              void* d_out, int out_size)
{
    const float *event = nullptr, *w_ih0 = nullptr, *w_ih = nullptr, *whh = nullptr;
    const float *b_ih = nullptr, *b_hh = nullptr, *w_out = nullptr, *b_out = nullptr;
    for (int i = 0; i < n_in; i++) {
        long long s = in_sizes[i];
        const float* p = (const float*)d_in[i];
        if      (s == 2048)              event = p;
        else if (s == 8192)              w_ih0 = p;
        else if (s == 50331648LL)        w_ih  = p;   // 3*8192*2048
        else if (s == 67108864LL)        whh   = p;   // 4*8192*2048
        else if (s == 32768)             { if (!b_ih) b_ih = p; else b_hh = p; }
        else if (s == 4096)              w_out = p;
        else if (s == 2)                 b_out = p;
    }

    cudaFuncSetAttribute(lstm_fp16_kernel,
                         cudaFuncAttributeMaxDynamicSharedMemorySize, SMEM_DYN);

    bias_kernel<<<(LAYERS * G4 + 255) / 256, 256>>>(b_ih, b_hh);
    convert_whh_kernel<<<LAYERS * G4, 512>>>(whh);
    convert_wih_kernel<<<(LAYERS - 1) * G4, 512>>>(w_ih);
    xw0_kernel<<<TT, 256>>>(event, w_ih0);
    lstm_fp16_kernel<<<NB, RTH, SMEM_DYN>>>(0);

    for (int l = 1; l < LAYERS; l++) {
        __half* wb = nullptr;
        cudaGetSymbolAddress((void**)&wb, g_wih16);    // address-of, not allocation
        xw_gemm16_kernel<<<dim3(G4 / 128, TT / 128), 256>>>(wb + (size_t)(l - 1) * G4 * H2);
        lstm_fp16_kernel<<<NB, RTH, SMEM_DYN>>>(l);
    }

    out_kernel<<<1, 256>>>(w_out, b_out, (float*)d_out);
}